// round 8
// baseline (speedup 1.0000x reference)
#include <cuda_runtime.h>
#include <cuda_bf16.h>
#include <cstdint>

#define N_NODES   100000
#define N_EDGES   625000
#define HIDDEN    128
#define N_LAYERS  4
#define NUM_GRAPHS 512
#define GRID_M    ((N_NODES + 127) / 128)
#define SCAN_BLKS ((N_NODES + 1023) / 1024)   // 98

// Scratch (device globals; allocation inside kernel_launch is forbidden)
__device__ float d_zA[N_NODES * HIDDEN];
__device__ float d_zB[N_NODES * HIDDEN];
__device__ float d_g[NUM_GRAPHS * HIDDEN];
__device__ int   d_gcnt[NUM_GRAPHS];
// Composite conv weights, transposed + bf16 hi/lo split: [4 mats][n=128][k=128]
// mat 0 = W1_0^T ; mat l = (W2_{l-1} @ W1_l)^T for l=1..3
__device__ __nv_bfloat16 d_WBhi[4 * HIDDEN * HIDDEN];
__device__ __nv_bfloat16 d_WBlo[4 * HIDDEN * HIDDEN];
__device__ float d_cvec[4 * HIDDEN];   // c_l = b2_{l-1} @ W1_l (c_0 = 0)
// CSR (by dst) machinery
__device__ int d_deg[N_NODES];
__device__ int d_rowptr[N_NODES + 1];
__device__ int d_wpos[N_NODES];
__device__ int d_csr_src[N_EDGES];
__device__ int d_bsum[SCAN_BLKS];
__device__ int d_boff[SCAN_BLKS];

__device__ __forceinline__ float* sel_buf(int s) { return s == 0 ? d_zA : d_zB; }

__device__ __forceinline__ uint32_t smem_u32(const void* p) {
    uint32_t a;
    asm("{ .reg .u64 t; cvta.to.shared.u64 t, %1; cvt.u32.u64 %0, t; }"
        : "=r"(a) : "l"(p));
    return a;
}
// SW128-style swizzle: XOR bits[9:7] into bits[6:4]. Apply to FULL byte offset.
__device__ __forceinline__ uint32_t swz(uint32_t b) {
    return b ^ ((b >> 3) & 0x70);
}

// ---------------------------------------------------------------------------
// Weight prep
// ---------------------------------------------------------------------------
__global__ void prep_w0_kernel(const float* __restrict__ W1) {
    int t = blockIdx.x * blockDim.x + threadIdx.x;
    if (t >= HIDDEN * HIDDEN) return;
    int n = t & 127, k = t >> 7;
    float v = W1[k * HIDDEN + n];
    __nv_bfloat16 hi = __float2bfloat16(v);
    d_WBhi[n * 128 + k] = hi;
    d_WBlo[n * 128 + k] = __float2bfloat16(v - __bfloat162float(hi));
}
__global__ void prep_compose_kernel(const float* __restrict__ W1,
                                    const float* __restrict__ W2) {
    int t = blockIdx.x * blockDim.x + threadIdx.x;
    if (t >= 3 * HIDDEN * HIDDEN) return;
    int l = 1 + (t >> 14);
    int idx = t & 16383;
    int n = idx & 127, k = idx >> 7;
    const float* W2r = W2 + (l - 1) * HIDDEN * HIDDEN + k * HIDDEN;
    const float* W1m = W1 + l * HIDDEN * HIDDEN;
    float s = 0.f;
#pragma unroll 8
    for (int j = 0; j < HIDDEN; j++) s = fmaf(W2r[j], W1m[j * HIDDEN + n], s);
    __nv_bfloat16 hi = __float2bfloat16(s);
    d_WBhi[l * 16384 + n * 128 + k] = hi;
    d_WBlo[l * 16384 + n * 128 + k] = __float2bfloat16(s - __bfloat162float(hi));
}
__global__ void prep_cvec_kernel(const float* __restrict__ W1,
                                 const float* __restrict__ b2) {
    int t = blockIdx.x * blockDim.x + threadIdx.x;
    if (t >= 4 * HIDDEN) return;
    int l = t >> 7, n = t & 127;
    float s = 0.f;
    if (l > 0) {
        const float* b2r = b2 + (l - 1) * HIDDEN;
        const float* W1m = W1 + l * HIDDEN * HIDDEN;
#pragma unroll 8
        for (int j = 0; j < HIDDEN; j++) s = fmaf(b2r[j], W1m[j * HIDDEN + n], s);
    }
    d_cvec[t] = s;
}

// ---------------------------------------------------------------------------
// MMA helpers
// ---------------------------------------------------------------------------
__device__ __forceinline__ void mma_bf16(float* c, const uint32_t* a,
                                         const uint32_t* b) {
    asm volatile(
        "mma.sync.aligned.m16n8k16.row.col.f32.bf16.bf16.f32 "
        "{%0,%1,%2,%3}, {%4,%5,%6,%7}, {%8,%9}, {%0,%1,%2,%3};"
        : "+f"(c[0]), "+f"(c[1]), "+f"(c[2]), "+f"(c[3])
        : "r"(a[0]), "r"(a[1]), "r"(a[2]), "r"(a[3]), "r"(b[0]), "r"(b[1]));
}
#define LDSM_X4(r, addr) \
    asm volatile("ldmatrix.sync.aligned.m8n8.x4.shared.b16 {%0,%1,%2,%3}, [%4];" \
                 : "=r"((r)[0]), "=r"((r)[1]), "=r"((r)[2]), "=r"((r)[3]) \
                 : "r"(addr))

// smem: A-hi (2x16KB k-chunks) at 0, A-lo at +32KB. Total 64KB.
#define SA_LO 32768
#define SMEMB 65536

// ---------------------------------------------------------------------------
// Fused layer: gather z (+self) -> ONE 3-term GEMM -> relu(.+deg'*c+b1) -> z'
// CTA: 128 nodes, 512 threads (16 warps, 32x32 MMA tiles). B frags via LDG.
// ---------------------------------------------------------------------------
template <bool EMB>
__global__ __launch_bounds__(512, 2) void layer_kernel(
    int insel, int outsel, int widx,
    const float* __restrict__ b1,
    const int* __restrict__ x, const float* __restrict__ node_emb) {
    const float* __restrict__ zin = sel_buf(insel);
    float* __restrict__ zout = sel_buf(outsel);
    const float* __restrict__ cvec = d_cvec + widx * HIDDEN;

    extern __shared__ char sm[];
    uint32_t sbase = smem_u32(sm);

    int tid = threadIdx.x;
    int lane = tid & 31;
    int wid = tid >> 5;
    int wm = (wid & 3) * 32;
    int wn = (wid >> 2) * 32;
    int bm = blockIdx.x * 128;

    // ============ gather: smem A = split(z[node] + sum z[src]) ============
    // warp handles 8 rows; lane covers 4 columns (float4) of each row.
    {
        const float* __restrict__ SRC = EMB ? node_emb : zin;
        int c4 = lane << 2;
        uint32_t chb = (uint32_t)(c4 >> 6) * 16384;
        uint32_t cbyte = (uint32_t)((c4 & 63) << 1);
#pragma unroll 2
        for (int i = 0; i < 8; i++) {
            int row = wid * 8 + i;
            int node = bm + row;
            float4 acc = make_float4(0.f, 0.f, 0.f, 0.f);
            if (node < N_NODES) {
                int self = EMB ? __ldg(&x[node]) : node;
                acc = *(const float4*)&SRC[self * 128 + c4];
                int beg = __ldg(&d_rowptr[node]);
                int end = __ldg(&d_rowptr[node + 1]);
                int j = beg;
                for (; j + 4 <= end; j += 4) {
                    int s0 = __ldg(&d_csr_src[j + 0]);
                    int s1 = __ldg(&d_csr_src[j + 1]);
                    int s2 = __ldg(&d_csr_src[j + 2]);
                    int s3 = __ldg(&d_csr_src[j + 3]);
                    if (EMB) {
                        s0 = __ldg(&x[s0]); s1 = __ldg(&x[s1]);
                        s2 = __ldg(&x[s2]); s3 = __ldg(&x[s3]);
                    }
                    float4 v0 = *(const float4*)&SRC[s0 * 128 + c4];
                    float4 v1 = *(const float4*)&SRC[s1 * 128 + c4];
                    float4 v2 = *(const float4*)&SRC[s2 * 128 + c4];
                    float4 v3 = *(const float4*)&SRC[s3 * 128 + c4];
                    acc.x += (v0.x + v1.x) + (v2.x + v3.x);
                    acc.y += (v0.y + v1.y) + (v2.y + v3.y);
                    acc.z += (v0.z + v1.z) + (v2.z + v3.z);
                    acc.w += (v0.w + v1.w) + (v2.w + v3.w);
                }
                for (; j < end; j++) {
                    int s = __ldg(&d_csr_src[j]);
                    if (EMB) s = __ldg(&x[s]);
                    float4 v = *(const float4*)&SRC[s * 128 + c4];
                    acc.x += v.x; acc.y += v.y; acc.z += v.z; acc.w += v.w;
                }
            }
            float vv[4] = {acc.x, acc.y, acc.z, acc.w};
            union { __nv_bfloat16 b[4]; uint2 u; } H, L;
#pragma unroll
            for (int q = 0; q < 4; q++) {
                H.b[q] = __float2bfloat16(vv[q]);
                L.b[q] = __float2bfloat16(vv[q] - __bfloat162float(H.b[q]));
            }
            uint32_t off = chb + swz((uint32_t)(row * 128) + cbyte);
            *(uint2*)(sm + off) = H.u;
            *(uint2*)(sm + SA_LO + off) = L.u;
        }
    }
    __syncthreads();

    // ============ ONE GEMM (3-term split), B fragments direct from global ===
    float acc[2][4][4];
#pragma unroll
    for (int i = 0; i < 2; i++)
#pragma unroll
        for (int j = 0; j < 4; j++)
#pragma unroll
            for (int q = 0; q < 4; q++) acc[i][j][q] = 0.f;

    const __nv_bfloat16* __restrict__ Whi = d_WBhi + widx * 16384;
    const __nv_bfloat16* __restrict__ Wlo = d_WBlo + widx * 16384;

    // per-lane B addressing: n = wn + nj*8 + lane/4, k = ks*16 + 2*(lane&3)
    int bn = wn + (lane >> 2);
    int bk = (lane & 3) << 1;

#pragma unroll 1
    for (int ks = 0; ks < 8; ks++) {
        uint32_t ahi[2][4], alo[2][4];
#pragma unroll
        for (int mi = 0; mi < 2; mi++) {
            int r = wm + mi * 16 + (lane & 15);
            int kl = (ks & 3) * 16 + (lane >> 4) * 8;   // local k in chunk
            uint32_t ad = sbase + (uint32_t)(ks >> 2) * 16384 +
                          swz((uint32_t)(r * 128) + (uint32_t)(kl * 2));
            LDSM_X4(ahi[mi], ad);
            LDSM_X4(alo[mi], ad + SA_LO);
        }
        int kg = ks * 16 + bk;
#pragma unroll
        for (int nj = 0; nj < 4; nj++) {
            const __nv_bfloat16* ph = &Whi[(bn + nj * 8) * 128 + kg];
            const __nv_bfloat16* pl = &Wlo[(bn + nj * 8) * 128 + kg];
            uint32_t bh[2], bl[2];
            bh[0] = __ldg((const uint32_t*)ph);
            bh[1] = __ldg((const uint32_t*)(ph + 8));
            bl[0] = __ldg((const uint32_t*)pl);
            bl[1] = __ldg((const uint32_t*)(pl + 8));
#pragma unroll
            for (int mi = 0; mi < 2; mi++) {
                mma_bf16(acc[mi][nj], ahi[mi], bh);
                mma_bf16(acc[mi][nj], ahi[mi], bl);
                mma_bf16(acc[mi][nj], alo[mi], bh);
            }
        }
    }

    // ============ epilogue: z' = relu(acc + deg'*c + b1) ============
    int g = lane >> 2, tg = lane & 3;
    float degp[2][2];
#pragma unroll
    for (int mi = 0; mi < 2; mi++)
#pragma unroll
        for (int h = 0; h < 2; h++) {
            int row = bm + wm + mi * 16 + g + h * 8;
            degp[mi][h] = (row < N_NODES)
                ? (float)(__ldg(&d_rowptr[row + 1]) - __ldg(&d_rowptr[row]) + 1)
                : 0.f;
        }
#pragma unroll
    for (int nj = 0; nj < 4; nj++) {
        int col = wn + nj * 8 + tg * 2;
        float2 bb = *(const float2*)&b1[col];
        float2 cv = *(const float2*)&cvec[col];
#pragma unroll
        for (int mi = 0; mi < 2; mi++) {
            int r0 = bm + wm + mi * 16 + g;
            float2 o0, o1;
            o0.x = fmaxf(acc[mi][nj][0] + degp[mi][0] * cv.x + bb.x, 0.f);
            o0.y = fmaxf(acc[mi][nj][1] + degp[mi][0] * cv.y + bb.y, 0.f);
            o1.x = fmaxf(acc[mi][nj][2] + degp[mi][1] * cv.x + bb.x, 0.f);
            o1.y = fmaxf(acc[mi][nj][3] + degp[mi][1] * cv.y + bb.y, 0.f);
            if (r0 < N_NODES)     *(float2*)&zout[r0 * 128 + col] = o0;
            if (r0 + 8 < N_NODES) *(float2*)&zout[(r0 + 8) * 128 + col] = o1;
        }
    }
}

// ---------------------------------------------------------------------------
// CSR build (by dst): histogram -> 3-phase grid scan -> fill
// ---------------------------------------------------------------------------
__global__ void zero_deg_kernel() {
    int t = blockIdx.x * blockDim.x + threadIdx.x;
    if (t < N_NODES) d_deg[t] = 0;
}
__global__ void hist_kernel(const int* __restrict__ dst) {
    int e = blockIdx.x * blockDim.x + threadIdx.x;
    if (e < N_EDGES) atomicAdd(&d_deg[dst[e]], 1);
}
__global__ __launch_bounds__(1024) void scanA_kernel() {
    __shared__ int ws[32];
    int i = blockIdx.x * 1024 + threadIdx.x;
    int v = (i < N_NODES) ? d_deg[i] : 0;
    int lane = threadIdx.x & 31, w = threadIdx.x >> 5;
#pragma unroll
    for (int o = 16; o; o >>= 1) v += __shfl_down_sync(0xffffffffu, v, o);
    if (lane == 0) ws[w] = v;
    __syncthreads();
    if (w == 0) {
        int s = ws[lane];
#pragma unroll
        for (int o = 16; o; o >>= 1) s += __shfl_down_sync(0xffffffffu, s, o);
        if (lane == 0) d_bsum[blockIdx.x] = s;
    }
}
__global__ __launch_bounds__(128) void scanB_kernel() {
    __shared__ int s[SCAN_BLKS];
    int t = threadIdx.x;
    if (t < SCAN_BLKS) s[t] = d_bsum[t];
    __syncthreads();
    if (t == 0) {
        int r = 0;
#pragma unroll 4
        for (int i = 0; i < SCAN_BLKS; i++) { int v = s[i]; s[i] = r; r += v; }
    }
    __syncthreads();
    if (t < SCAN_BLKS) d_boff[t] = s[t];
}
__global__ __launch_bounds__(1024) void scanC_kernel() {
    __shared__ int ws[32];
    int i = blockIdx.x * 1024 + threadIdx.x;
    int v = (i < N_NODES) ? d_deg[i] : 0;
    int lane = threadIdx.x & 31, w = threadIdx.x >> 5;
    int x = v;
#pragma unroll
    for (int o = 1; o < 32; o <<= 1) {
        int y = __shfl_up_sync(0xffffffffu, x, o);
        if (lane >= o) x += y;
    }
    if (lane == 31) ws[w] = x;
    __syncthreads();
    if (w == 0) {
        int y = ws[lane];
#pragma unroll
        for (int o = 1; o < 32; o <<= 1) {
            int z = __shfl_up_sync(0xffffffffu, y, o);
            if (lane >= o) y += z;
        }
        ws[lane] = y;
    }
    __syncthreads();
    int incl = x + (w ? ws[w - 1] : 0);
    int base = d_boff[blockIdx.x];
    int excl = base + incl - v;
    if (i < N_NODES) {
        d_rowptr[i] = excl;
        d_wpos[i] = excl;
        if (i == N_NODES - 1) d_rowptr[N_NODES] = excl + v;
    }
}
__global__ void fill_kernel(const int* __restrict__ src,
                            const int* __restrict__ dst) {
    int e = blockIdx.x * blockDim.x + threadIdx.x;
    if (e >= N_EDGES) return;
    int p = atomicAdd(&d_wpos[dst[e]], 1);
    d_csr_src[p] = src[e];
}

// ---------------------------------------------------------------------------
// Graph pooling (of z_last) + head (fold W2_3/b2_3, then MLP)
// ---------------------------------------------------------------------------
__global__ void zero_g_kernel() {
    int t = blockIdx.x * blockDim.x + threadIdx.x;
    if (t < NUM_GRAPHS * HIDDEN) d_g[t] = 0.f;
    if (t < NUM_GRAPHS) d_gcnt[t] = 0;
}
__global__ void pool_kernel(const int* __restrict__ batch) {
    int t = blockIdx.x * blockDim.x + threadIdx.x;
    int node = t >> 5;
    if (node >= N_NODES) return;
    int lane = t & 31;
    int gidx = __ldg(&batch[node]);
    float4 v = *(const float4*)&d_zB[node * HIDDEN + (lane << 2)];
    float* p = &d_g[gidx * HIDDEN + (lane << 2)];
    asm volatile("red.global.add.v4.f32 [%0], {%1,%2,%3,%4};"
                 :: "l"(p), "f"(v.x), "f"(v.y), "f"(v.z), "f"(v.w)
                 : "memory");
    if (lane == 0) atomicAdd(&d_gcnt[gidx], 1);
}
__global__ __launch_bounds__(128) void head_kernel(
    const float* __restrict__ W2c, const float* __restrict__ b2c,
    const float* __restrict__ W1, const float* __restrict__ b1,
    const float* __restrict__ W2, const float* __restrict__ b2,
    const float* __restrict__ W3, const float* __restrict__ b3,
    float* __restrict__ out) {
    __shared__ float sg[128];
    __shared__ float gh[128];
    __shared__ float s1[64];
    int g = blockIdx.x;
    int tid = threadIdx.x;

    sg[tid] = d_g[g * 128 + tid];
    __syncthreads();
    float cnt = (float)d_gcnt[g];

    float a = cnt * __ldg(&b2c[tid]);
#pragma unroll 8
    for (int k = 0; k < 128; k++) a = fmaf(sg[k], W2c[k * 128 + tid], a);
    gh[tid] = a;
    __syncthreads();

    if (tid < 64) {
        float acc = __ldg(&b1[tid]);
#pragma unroll 8
        for (int k = 0; k < 128; k++) acc = fmaf(gh[k], W1[k * 64 + tid], acc);
        s1[tid] = fmaxf(acc, 0.f);
    }
    __syncthreads();

    if (tid < 32) {
        float a2 = __ldg(&b2[tid]);
#pragma unroll 8
        for (int k = 0; k < 64; k++) a2 = fmaf(s1[k], W2[k * 32 + tid], a2);
        a2 = fmaxf(a2, 0.f);
        float t3 = a2 * __ldg(&W3[tid]);
#pragma unroll
        for (int o = 16; o; o >>= 1) t3 += __shfl_down_sync(0xffffffffu, t3, o);
        if (tid == 0) out[g] = t3 + __ldg(&b3[0]);
    }
}

// ---------------------------------------------------------------------------
extern "C" void kernel_launch(void* const* d_in, const int* in_sizes, int n_in,
                              void* d_out, int out_size) {
    const int*   x        = (const int*)d_in[0];
    const int*   edge_idx = (const int*)d_in[1];
    const int*   src      = edge_idx;
    const int*   dst      = edge_idx + N_EDGES;
    const int*   batch    = (const int*)d_in[3];
    const float* node_emb = (const float*)d_in[4];
    // d_in[2] (edge_attr) and d_in[5] (edge_emb) are dead in the reference.
    const float* conv_W1  = (const float*)d_in[6];
    const float* conv_b1  = (const float*)d_in[7];
    const float* conv_W2  = (const float*)d_in[8];
    const float* conv_b2  = (const float*)d_in[9];
    const float* mlp_W1   = (const float*)d_in[10];
    const float* mlp_b1   = (const float*)d_in[11];
    const float* mlp_W2   = (const float*)d_in[12];
    const float* mlp_b2   = (const float*)d_in[13];
    const float* mlp_W3   = (const float*)d_in[14];
    const float* mlp_b3   = (const float*)d_in[15];
    float* out = (float*)d_out;

    cudaFuncSetAttribute(layer_kernel<true>,
                         cudaFuncAttributeMaxDynamicSharedMemorySize, SMEMB);
    cudaFuncSetAttribute(layer_kernel<false>,
                         cudaFuncAttributeMaxDynamicSharedMemorySize, SMEMB);

    prep_w0_kernel<<<(HIDDEN * HIDDEN + 255) / 256, 256>>>(conv_W1);
    prep_compose_kernel<<<(3 * HIDDEN * HIDDEN + 255) / 256, 256>>>(conv_W1, conv_W2);
    prep_cvec_kernel<<<2, 256>>>(conv_W1, conv_b2);
    zero_deg_kernel<<<(N_NODES + 255) / 256, 256>>>();
    hist_kernel<<<(N_EDGES + 255) / 256, 256>>>(dst);
    scanA_kernel<<<SCAN_BLKS, 1024>>>();
    scanB_kernel<<<1, 128>>>();
    scanC_kernel<<<SCAN_BLKS, 1024>>>();
    fill_kernel<<<(N_EDGES + 255) / 256, 256>>>(src, dst);

    // z-state ping-pong: L0 emb->zA, L1 zA->zB, L2 zB->zA, L3 zA->zB
    layer_kernel<true><<<GRID_M, 512, SMEMB>>>(
        0, 0, 0, conv_b1 + 0 * HIDDEN, x, node_emb);
    layer_kernel<false><<<GRID_M, 512, SMEMB>>>(
        0, 1, 1, conv_b1 + 1 * HIDDEN, x, node_emb);
    layer_kernel<false><<<GRID_M, 512, SMEMB>>>(
        1, 0, 2, conv_b1 + 2 * HIDDEN, x, node_emb);
    layer_kernel<false><<<GRID_M, 512, SMEMB>>>(
        0, 1, 3, conv_b1 + 3 * HIDDEN, x, node_emb);

    zero_g_kernel<<<(NUM_GRAPHS * HIDDEN + 255) / 256, 256>>>();
    pool_kernel<<<(N_NODES * 32 + 255) / 256, 256>>>(batch);
    head_kernel<<<NUM_GRAPHS, 128>>>(
        conv_W2 + 3 * HIDDEN * HIDDEN, conv_b2 + 3 * HIDDEN,
        mlp_W1, mlp_b1, mlp_W2, mlp_b2, mlp_W3, mlp_b3, out);
}